// round 14
// baseline (speedup 1.0000x reference)
#include <cuda_runtime.h>
#include <cuda_fp16.h>
#include <math.h>
#include <stdint.h>

#define BSZ 64
#define MM  2048
#define DD  1024
#define HH  1024
#define HT  8                 // h-tiles (HH/128)
#define KC  64                // k per stage
#define NSTG (DD / KC)        // 16
#define NBUF 3                // 3-stage cp.async ring

// stage tile offsets: each image 128 rows x 128B = 16 KB (A, B)
#define T_A 0
#define T_B 16384
#define STAGE_B 32768
#define OFF_QV   0
#define OFF_VV   512
#define OFF_RED  1024
#define OFF_TILE 2048
#define SMEM_TOTAL (OFF_TILE + NBUF * STAGE_B)   // 100352 B -> 2 CTAs/SM

__device__ float g_qproj[BSZ * HH];
__device__ float g_part[HT * BSZ * MM];
__device__ __half g_bh[HH * DD];                // Wm fp16 image (k-major)
__device__ __half g_ah[(size_t)BSZ * MM * DD];  // memory fp16 image (256 MB)

// ---------------------------------------------------------------------------
__device__ __forceinline__ uint32_t smem_u32(const void* p) {
    uint32_t a;
    asm("{ .reg .u64 t; cvta.to.shared.u64 t, %1; cvt.u32.u64 %0, t; }" : "=r"(a) : "l"(p));
    return a;
}
#define SW(o) ((o) ^ (((o) >> 3) & 0x70))

#define LDSM4(r, addr) \
    asm volatile("ldmatrix.sync.aligned.m8n8.x4.shared.b16 {%0,%1,%2,%3}, [%4];" \
        : "=r"((r)[0]), "=r"((r)[1]), "=r"((r)[2]), "=r"((r)[3]) : "r"(addr))

#define MMA16816(d, a, b0v, b1v) \
    asm volatile("mma.sync.aligned.m16n8k16.row.col.f32.f16.f16.f32 " \
        "{%0,%1,%2,%3}, {%4,%5,%6,%7}, {%8,%9}, {%0,%1,%2,%3};" \
        : "+f"((d)[0]), "+f"((d)[1]), "+f"((d)[2]), "+f"((d)[3]) \
        : "r"((a)[0]), "r"((a)[1]), "r"((a)[2]), "r"((a)[3]), "r"(b0v), "r"(b1v))

#define CP16(dst, src) \
    asm volatile("cp.async.cg.shared.global [%0], [%1], 16;" :: "r"(dst), "l"(src) : "memory")
#define CP_COMMIT asm volatile("cp.async.commit_group;" ::: "memory")
#define CP_WAIT0  asm volatile("cp.async.wait_group 0;"  ::: "memory")
#define CP_WAIT1  asm volatile("cp.async.wait_group 1;"  ::: "memory")

__device__ __forceinline__ float tanh_fast(float x) {
    float e, r;
    asm("ex2.approx.f32 %0, %1;" : "=f"(e) : "f"(x * 2.8853900817779268f));   // e^{2x}
    asm("rcp.approx.f32 %0, %1;" : "=f"(r) : "f"(e + 1.0f));
    return fmaf(-2.0f, r, 1.0f);
}

// convert 8 fp32 -> 16B (8 fp16)
__device__ __forceinline__ uint4 cvt8h(const float4 a, const float4 b) {
    __half2 h0 = __floats2half2_rn(a.x, a.y);
    __half2 h1 = __floats2half2_rn(a.z, a.w);
    __half2 h2 = __floats2half2_rn(b.x, b.y);
    __half2 h3 = __floats2half2_rn(b.z, b.w);
    return make_uint4(*(uint32_t*)&h0, *(uint32_t*)&h1, *(uint32_t*)&h2, *(uint32_t*)&h3);
}

// ---------------------------------------------------------------------------
// Prep: memory -> fp16 image
// ---------------------------------------------------------------------------
__global__ __launch_bounds__(256) void prep_a_kernel(const float* __restrict__ mem) {
    const size_t i = ((size_t)blockIdx.x * 256 + threadIdx.x) * 8;
    const float4 a = *(const float4*)(mem + i);
    const float4 b = *(const float4*)(mem + i + 4);
    *(uint4*)(g_ah + i) = cvt8h(a, b);
}

// ---------------------------------------------------------------------------
// Prep: Wm -> fp16 image (k-major)
// ---------------------------------------------------------------------------
__global__ __launch_bounds__(128) void prep_b_kernel(const float* __restrict__ Wm) {
    const int h = blockIdx.x;
    const int d = threadIdx.x * 8;
    const float4 a = *(const float4*)(Wm + (size_t)h * DD + d);
    const float4 b = *(const float4*)(Wm + (size_t)h * DD + d + 4);
    *(uint4*)(g_bh + (size_t)h * DD + d) = cvt8h(a, b);
}

// ---------------------------------------------------------------------------
// qproj
// ---------------------------------------------------------------------------
__global__ __launch_bounds__(128) void qproj_kernel(
    const float* __restrict__ query, const float* __restrict__ Wq,
    const float* __restrict__ bq) {
    __shared__ float qs[DD];
    const int b = blockIdx.x, h0 = blockIdx.y * 128, tid = threadIdx.x;
    for (int i = tid; i < DD; i += 128) qs[i] = query[b * DD + i];
    __syncthreads();
    const int warp = tid >> 5, lane = tid & 31;
    for (int hl = warp; hl < 128; hl += 4) {
        const int h = h0 + hl;
        const float* w = Wq + (size_t)h * DD;
        float s = 0.f;
        #pragma unroll 8
        for (int j = lane; j < DD; j += 32) s += qs[j] * w[j];
        #pragma unroll
        for (int o = 16; o > 0; o >>= 1) s += __shfl_xor_sync(0xffffffffu, s, o);
        if (lane == 0) g_qproj[b * HH + h] = s + bq[h];
    }
}

// ---------------------------------------------------------------------------
// HMMA fp16 single-pass GEMM, 3-stage ring, B-fragment software pipeline
// grid (HT=8, 1024), 256 threads (8 warps: 4m x 2n, warp tile 32x64)
// ---------------------------------------------------------------------------
__global__ __launch_bounds__(256, 2) void attn_gemm_hmma(const float* __restrict__ v) {
    extern __shared__ char smem[];
    const uint32_t sb = smem_u32(smem);
    const int tid = threadIdx.x;
    const int h0 = blockIdx.x * 128;
    const int row0 = blockIdx.y * 128;
    const int batch = row0 >> 11;

    float* qv = (float*)(smem + OFF_QV);
    float* vv = (float*)(smem + OFF_VV);
    float* sred = (float*)(smem + OFF_RED);
    if (tid < 128) {
        qv[tid] = g_qproj[batch * HH + h0 + tid];
        vv[tid] = v[h0 + tid];
    }

    // copy-thread mapping (slimmed: single base per thread, j folds as +4096/j*32*DD)
    const int crow = tid >> 3;          // 0..31 (+32 per j)
    const int ccu  = tid & 7;           // 16B unit within 128B row
    const uint32_t cp_o0 = SW((uint32_t)(crow * 128 + ccu * 16));  // +4096*j exact
    const __half* ap0 = g_ah + (size_t)(row0 + crow) * DD + ccu * 8;
    const __half* bp0 = g_bh + (size_t)(h0 + crow) * DD + ccu * 8;

    const int warp = tid >> 5, lane = tid & 31;
    const int wm = (warp >> 1) * 32;
    const int wn = (warp & 1) * 64;
    const int lrow = lane & 15;
    const int lkb  = (lane >> 4) * 16;

    // hoisted LDSM swizzled bases; SW(o + kk*32) == SW(o) ^ (kk*32) here
    uint32_t a_base[2], b_base[4];
    #pragma unroll
    for (int mi = 0; mi < 2; mi++)
        a_base[mi] = SW((uint32_t)((wm + mi * 16 + lrow) * 128 + lkb));
    #pragma unroll
    for (int g = 0; g < 4; g++)
        b_base[g] = SW((uint32_t)((wn + g * 16 + lrow) * 128 + lkb));

    float acc[2][8][4];
    #pragma unroll
    for (int i = 0; i < 2; i++)
        #pragma unroll
        for (int j = 0; j < 8; j++)
            #pragma unroll
            for (int k = 0; k < 4; k++) acc[i][j][k] = 0.f;

    // ---- prologue: stages 0 and 1 ----
    #pragma unroll
    for (int p = 0; p < 2; p++) {
        const uint32_t bb = sb + OFF_TILE + p * STAGE_B;
        #pragma unroll
        for (int j = 0; j < 4; j++) {
            CP16(bb + T_A + cp_o0 + j * 4096, ap0 + (size_t)j * (32 * DD) + p * KC);
            CP16(bb + T_B + cp_o0 + j * 4096, bp0 + (size_t)j * (32 * DD) + p * KC);
        }
        CP_COMMIT;
    }

    // ---- main loop ----
    int rslot = 0, wslot = 2;
    for (int s = 0; s < NSTG; s++) {
        if (s == NSTG - 1) { CP_WAIT0; } else { CP_WAIT1; }
        __syncthreads();   // slot (s-1)%3 fully consumed by all warps

        if (s + 2 < NSTG) {
            const uint32_t bb = sb + OFF_TILE + wslot * STAGE_B;
            #pragma unroll
            for (int j = 0; j < 4; j++) {
                CP16(bb + T_A + cp_o0 + j * 4096, ap0 + (size_t)j * (32 * DD) + (s + 2) * KC);
                CP16(bb + T_B + cp_o0 + j * 4096, bp0 + (size_t)j * (32 * DD) + (s + 2) * KC);
            }
            CP_COMMIT;
        }

        // compute slot rslot — B fragments double-buffered across kk
        const uint32_t abase = sb + OFF_TILE + rslot * STAGE_B + T_A;
        const uint32_t bbase = sb + OFF_TILE + rslot * STAGE_B + T_B;
        uint32_t bhb[2][4][4];
        #pragma unroll
        for (int g = 0; g < 4; g++)
            LDSM4(bhb[0][g], bbase + b_base[g]);       // kk=0 B
        #pragma unroll
        for (int kk = 0; kk < 4; kk++) {
            const int cb = kk & 1, nb = cb ^ 1;
            uint32_t ah[2][4];
            #pragma unroll
            for (int mi = 0; mi < 2; mi++)
                LDSM4(ah[mi], abase + (a_base[mi] ^ (uint32_t)(kk * 32)));
            if (kk < 3) {
                const uint32_t kko = (uint32_t)((kk + 1) * 32);
                #pragma unroll
                for (int g = 0; g < 4; g++)
                    LDSM4(bhb[nb][g], bbase + (b_base[g] ^ kko));
            }
            #pragma unroll
            for (int mi = 0; mi < 2; mi++)
                #pragma unroll
                for (int g = 0; g < 4; g++)
                    #pragma unroll
                    for (int sl = 0; sl < 2; sl++) {
                        const int nj = g * 2 + sl;
                        MMA16816(acc[mi][nj], ah[mi], bhb[cb][g][sl], bhb[cb][g][sl + 2]);
                    }
        }

        rslot = (rslot == NBUF - 1) ? 0 : rslot + 1;
        wslot = (wslot == NBUF - 1) ? 0 : wslot + 1;
    }

    // ---- epilogue: tanh(c + qp) * v, row-reduce ----
    #pragma unroll
    for (int mi = 0; mi < 2; mi++)
        #pragma unroll
        for (int hf = 0; hf < 2; hf++) {
            float s = 0.f;
            #pragma unroll
            for (int nj = 0; nj < 8; nj++)
                #pragma unroll
                for (int c = 0; c < 2; c++) {
                    const int h = wn + nj * 8 + ((lane & 3) << 1) + c;
                    const float cc = acc[mi][nj][hf * 2 + c] + qv[h];
                    s += tanh_fast(cc) * vv[h];
                }
            s += __shfl_xor_sync(0xffffffffu, s, 1);
            s += __shfl_xor_sync(0xffffffffu, s, 2);
            if ((lane & 3) == 0)
                sred[(wm + mi * 16 + hf * 8 + (lane >> 2)) * 2 + (warp & 1)] = s;
        }
    __syncthreads();
    if (tid < 128)
        g_part[blockIdx.x * (BSZ * MM) + row0 + tid] = sred[tid * 2] + sred[tid * 2 + 1];
}

// ---------------------------------------------------------------------------
// softmax over M per batch (sums HT h-tile partials)
// ---------------------------------------------------------------------------
__global__ __launch_bounds__(256) void softmax_kernel(float* __restrict__ out_w) {
    __shared__ float sm[MM];
    __shared__ float red[256];
    const int b = blockIdx.x, tid = threadIdx.x;
    float lmax = -1e30f;
    for (int m = tid; m < MM; m += 256) {
        float s = 0.f;
        #pragma unroll
        for (int t = 0; t < HT; t++) s += g_part[t * (BSZ * MM) + b * MM + m];
        sm[m] = s;
        lmax = fmaxf(lmax, s);
    }
    red[tid] = lmax; __syncthreads();
    for (int o = 128; o > 0; o >>= 1) {
        if (tid < o) red[tid] = fmaxf(red[tid], red[tid + o]);
        __syncthreads();
    }
    const float mx = red[0];
    __syncthreads();
    float ls = 0.f;
    for (int m = tid; m < MM; m += 256) {
        const float e = expf(sm[m] - mx);
        sm[m] = e; ls += e;
    }
    red[tid] = ls; __syncthreads();
    for (int o = 128; o > 0; o >>= 1) {
        if (tid < o) red[tid] += red[tid + o];
        __syncthreads();
    }
    const float inv = 1.f / red[0];
    for (int m = tid; m < MM; m += 256) out_w[b * MM + m] = sm[m] * inv;
}

// ---------------------------------------------------------------------------
// weighted_memory from the fp16 image
// ---------------------------------------------------------------------------
__global__ __launch_bounds__(256) void weighted_mem_kernel(
    const float* __restrict__ w, float* __restrict__ out) {
    __shared__ float wsh[MM];
    __shared__ float sred[8 * 256];   // [i][tid]
    const int b = blockIdx.y, d0 = blockIdx.x * 128, tid = threadIdx.x;
    for (int i = tid; i < MM; i += 256) wsh[i] = w[b * MM + i];
    __syncthreads();
    const int lane = tid & 15;        // d-subtile (8 halves)
    const int grp  = tid >> 4;        // 16 m-groups
    const __half* base = g_ah + (size_t)b * MM * DD + d0 + lane * 8;
    float acc[8];
    #pragma unroll
    for (int i = 0; i < 8; i++) acc[i] = 0.f;
    #pragma unroll 4
    for (int m = grp; m < MM; m += 16) {
        const float ww = wsh[m];
        const uint4 x = *(const uint4*)(base + (size_t)m * DD);
        const __half2* hp = (const __half2*)&x;
        #pragma unroll
        for (int p = 0; p < 4; p++) {
            const float2 f = __half22float2(hp[p]);
            acc[2 * p]     = fmaf(ww, f.x, acc[2 * p]);
            acc[2 * p + 1] = fmaf(ww, f.y, acc[2 * p + 1]);
        }
    }
    #pragma unroll
    for (int i = 0; i < 8; i++) sred[i * 256 + tid] = acc[i];
    __syncthreads();
    if (tid < 128) {
        const int lane2 = tid >> 3, i = tid & 7;
        float s = 0.f;
        #pragma unroll
        for (int g = 0; g < 16; g++) s += sred[i * 256 + g * 16 + lane2];
        out[b * DD + d0 + lane2 * 8 + i] = s;
    }
}

// ---------------------------------------------------------------------------
extern "C" void kernel_launch(void* const* d_in, const int* in_sizes, int n_in,
                              void* d_out, int out_size) {
    const float* query  = (const float*)d_in[0];
    const float* memory = (const float*)d_in[1];
    const float* Wq     = (const float*)d_in[2];
    const float* bq     = (const float*)d_in[3];
    const float* Wm     = (const float*)d_in[4];
    const float* v      = (const float*)d_in[5];
    float* out = (float*)d_out;
    float* out_weights = out;                // [BSZ,1,MM]
    float* out_wmem    = out + BSZ * MM;     // [BSZ,1,DD]

    cudaFuncSetAttribute(attn_gemm_hmma,
                         cudaFuncAttributeMaxDynamicSharedMemorySize, SMEM_TOTAL);

    prep_a_kernel<<<(BSZ * MM * DD) / (256 * 8), 256>>>(memory);
    prep_b_kernel<<<HH, 128>>>(Wm);
    qproj_kernel<<<dim3(BSZ, HH / 128), 128>>>(query, Wq, bq);
    attn_gemm_hmma<<<dim3(HT, (BSZ * MM) / 128), 256, SMEM_TOTAL>>>(v);
    softmax_kernel<<<BSZ, 256>>>(out_weights);
    weighted_mem_kernel<<<dim3(DD / 128, BSZ), 256>>>(out_weights, out_wmem);
}

// round 15
// speedup vs baseline: 1.0765x; 1.0765x over previous
#include <cuda_runtime.h>
#include <cuda_fp16.h>
#include <math.h>
#include <stdint.h>

#define BSZ 64
#define MM  2048
#define DD  1024
#define HH  1024
#define HT  8                 // h-tiles (HH/128)
#define KC  64                // k per stage
#define NSTG (DD / KC)        // 16
#define NBUF 3                // 3-stage cp.async ring

// stage tile offsets: each image 128 rows x 128B = 16 KB (A, B)
#define T_A 0
#define T_B 16384
#define STAGE_B 32768
#define OFF_QV   0
#define OFF_VV   512
#define OFF_RED  1024
#define OFF_TILE 2048
#define SMEM_TOTAL (OFF_TILE + NBUF * STAGE_B)   // 100352 B -> 2 CTAs/SM

__device__ float g_qproj[BSZ * HH];
__device__ float g_part[HT * BSZ * MM];
__device__ __half g_bh[HH * DD];                // Wm fp16 image (k-major)
__device__ __half g_ah[(size_t)BSZ * MM * DD];  // memory fp16 image (256 MB)

// ---------------------------------------------------------------------------
__device__ __forceinline__ uint32_t smem_u32(const void* p) {
    uint32_t a;
    asm("{ .reg .u64 t; cvta.to.shared.u64 t, %1; cvt.u32.u64 %0, t; }" : "=r"(a) : "l"(p));
    return a;
}
#define SW(o) ((o) ^ (((o) >> 3) & 0x70))

#define LDSM4(r, addr) \
    asm volatile("ldmatrix.sync.aligned.m8n8.x4.shared.b16 {%0,%1,%2,%3}, [%4];" \
        : "=r"((r)[0]), "=r"((r)[1]), "=r"((r)[2]), "=r"((r)[3]) : "r"(addr))

#define MMA16816(d, a, b0v, b1v) \
    asm volatile("mma.sync.aligned.m16n8k16.row.col.f32.f16.f16.f32 " \
        "{%0,%1,%2,%3}, {%4,%5,%6,%7}, {%8,%9}, {%0,%1,%2,%3};" \
        : "+f"((d)[0]), "+f"((d)[1]), "+f"((d)[2]), "+f"((d)[3]) \
        : "r"((a)[0]), "r"((a)[1]), "r"((a)[2]), "r"((a)[3]), "r"(b0v), "r"(b1v))

#define CP16(dst, src) \
    asm volatile("cp.async.cg.shared.global [%0], [%1], 16;" :: "r"(dst), "l"(src) : "memory")
#define CP_COMMIT asm volatile("cp.async.commit_group;" ::: "memory")
#define CP_WAIT0  asm volatile("cp.async.wait_group 0;"  ::: "memory")
#define CP_WAIT1  asm volatile("cp.async.wait_group 1;"  ::: "memory")

__device__ __forceinline__ float tanh_fast(float x) {
    float e, r;
    asm("ex2.approx.f32 %0, %1;" : "=f"(e) : "f"(x * 2.8853900817779268f));   // e^{2x}
    asm("rcp.approx.f32 %0, %1;" : "=f"(r) : "f"(e + 1.0f));
    return fmaf(-2.0f, r, 1.0f);
}

// convert 8 fp32 -> 16B (8 fp16)
__device__ __forceinline__ uint4 cvt8h(const float4 a, const float4 b) {
    __half2 h0 = __floats2half2_rn(a.x, a.y);
    __half2 h1 = __floats2half2_rn(a.z, a.w);
    __half2 h2 = __floats2half2_rn(b.x, b.y);
    __half2 h3 = __floats2half2_rn(b.z, b.w);
    return make_uint4(*(uint32_t*)&h0, *(uint32_t*)&h1, *(uint32_t*)&h2, *(uint32_t*)&h3);
}

// ---------------------------------------------------------------------------
// Prep: memory -> fp16 image (16 floats per thread)
// ---------------------------------------------------------------------------
__global__ __launch_bounds__(256) void prep_a_kernel(const float* __restrict__ mem) {
    const size_t i = ((size_t)blockIdx.x * 256 + threadIdx.x) * 16;
    const float4 a0 = *(const float4*)(mem + i);
    const float4 b0 = *(const float4*)(mem + i + 4);
    const float4 a1 = *(const float4*)(mem + i + 8);
    const float4 b1 = *(const float4*)(mem + i + 12);
    *(uint4*)(g_ah + i)     = cvt8h(a0, b0);
    *(uint4*)(g_ah + i + 8) = cvt8h(a1, b1);
}

// ---------------------------------------------------------------------------
// Prep: Wm -> fp16 image (k-major)
// ---------------------------------------------------------------------------
__global__ __launch_bounds__(128) void prep_b_kernel(const float* __restrict__ Wm) {
    const int h = blockIdx.x;
    const int d = threadIdx.x * 8;
    const float4 a = *(const float4*)(Wm + (size_t)h * DD + d);
    const float4 b = *(const float4*)(Wm + (size_t)h * DD + d + 4);
    *(uint4*)(g_bh + (size_t)h * DD + d) = cvt8h(a, b);
}

// ---------------------------------------------------------------------------
// qproj: tiled mini-GEMM, L2-friendly (Wq read ~once total)
// grid (HH/64, BSZ/32), 256 threads; thread = 4b x 2h micro-tile
// ---------------------------------------------------------------------------
__global__ __launch_bounds__(256) void qproj_kernel(
    const float* __restrict__ query, const float* __restrict__ Wq,
    const float* __restrict__ bq) {
    __shared__ float qs[32][33];
    __shared__ float ws[64][33];
    const int h0 = blockIdx.x * 64;
    const int b0 = blockIdx.y * 32;
    const int tid = threadIdx.x;
    const int ti = tid & 7;        // 8 groups of 4 b
    const int tj = tid >> 3;       // 32 groups of 2 h

    float acc[4][2];
    #pragma unroll
    for (int x = 0; x < 4; x++) { acc[x][0] = 0.f; acc[x][1] = 0.f; }

    for (int k0 = 0; k0 < DD; k0 += 32) {
        __syncthreads();
        #pragma unroll
        for (int u = 0; u < 4; u++) {
            const int q = tid + u * 256;          // 0..1023
            const int bb = q >> 5, kk = q & 31;
            qs[bb][kk] = query[(size_t)(b0 + bb) * DD + k0 + kk];
        }
        #pragma unroll
        for (int u = 0; u < 8; u++) {
            const int q = tid + u * 256;          // 0..2047
            const int hh = q >> 5, kk = q & 31;
            ws[hh][kk] = Wq[(size_t)(h0 + hh) * DD + k0 + kk];
        }
        __syncthreads();
        #pragma unroll 8
        for (int kk = 0; kk < 32; kk++) {
            float qv[4], wv[2];
            #pragma unroll
            for (int x = 0; x < 4; x++) qv[x] = qs[ti * 4 + x][kk];
            wv[0] = ws[tj * 2][kk];
            wv[1] = ws[tj * 2 + 1][kk];
            #pragma unroll
            for (int x = 0; x < 4; x++) {
                acc[x][0] = fmaf(qv[x], wv[0], acc[x][0]);
                acc[x][1] = fmaf(qv[x], wv[1], acc[x][1]);
            }
        }
    }
    #pragma unroll
    for (int x = 0; x < 4; x++)
        #pragma unroll
        for (int y = 0; y < 2; y++) {
            const int h = h0 + tj * 2 + y;
            g_qproj[(b0 + ti * 4 + x) * HH + h] = acc[x][y] + bq[h];
        }
}

// ---------------------------------------------------------------------------
// HMMA fp16 single-pass GEMM, 3-stage cp.async ring, XOR-hoisted addresses
// (R13 structure verbatim — measured 662 us)
// grid (HT=8, 1024), 256 threads (8 warps: 4m x 2n, warp tile 32x64)
// ---------------------------------------------------------------------------
__global__ __launch_bounds__(256, 2) void attn_gemm_hmma(const float* __restrict__ v) {
    extern __shared__ char smem[];
    const uint32_t sb = smem_u32(smem);
    const int tid = threadIdx.x;
    const int h0 = blockIdx.x * 128;
    const int row0 = blockIdx.y * 128;
    const int batch = row0 >> 11;

    float* qv = (float*)(smem + OFF_QV);
    float* vv = (float*)(smem + OFF_VV);
    float* sred = (float*)(smem + OFF_RED);
    if (tid < 128) {
        qv[tid] = g_qproj[batch * HH + h0 + tid];
        vv[tid] = v[h0 + tid];
    }

    // copy-thread mapping: 16B units; q = tid + 256*j; row = q>>3, cu = q&7
    const int crow = tid >> 3;          // 0..31 (+32 per j)
    const int ccu  = tid & 7;           // 16B unit within 128B row
    uint32_t cp_o[4];
    const __half* ap[4];
    const __half* bp[4];
    #pragma unroll
    for (int j = 0; j < 4; j++) {
        const int row = crow + 32 * j;
        cp_o[j] = SW((uint32_t)(row * 128 + ccu * 16));
        ap[j] = g_ah + (size_t)(row0 + row) * DD + ccu * 8;
        bp[j] = g_bh + (size_t)(h0 + row) * DD + ccu * 8;
    }

    const int warp = tid >> 5, lane = tid & 31;
    const int wm = (warp >> 1) * 32;
    const int wn = (warp & 1) * 64;
    const int lrow = lane & 15;
    const int lkb  = (lane >> 4) * 16;

    // hoisted LDSM swizzled bases; SW(o + kk*32) == SW(o) ^ (kk*32) here
    uint32_t a_base[2], b_base[4];
    #pragma unroll
    for (int mi = 0; mi < 2; mi++)
        a_base[mi] = SW((uint32_t)((wm + mi * 16 + lrow) * 128 + lkb));
    #pragma unroll
    for (int g = 0; g < 4; g++)
        b_base[g] = SW((uint32_t)((wn + g * 16 + lrow) * 128 + lkb));

    float acc[2][8][4];
    #pragma unroll
    for (int i = 0; i < 2; i++)
        #pragma unroll
        for (int j = 0; j < 8; j++)
            #pragma unroll
            for (int k = 0; k < 4; k++) acc[i][j][k] = 0.f;

    // ---- prologue: stages 0 and 1 ----
    #pragma unroll
    for (int p = 0; p < 2; p++) {
        const uint32_t bb = sb + OFF_TILE + p * STAGE_B;
        #pragma unroll
        for (int j = 0; j < 4; j++) {
            CP16(bb + T_A + cp_o[j], ap[j]);
            CP16(bb + T_B + cp_o[j], bp[j]);
            ap[j] += KC; bp[j] += KC;
        }
        CP_COMMIT;
    }

    // ---- main loop: wait oldest -> sync -> prefetch s+2 -> compute s ----
    int rslot = 0, wslot = 2;
    for (int s = 0; s < NSTG; s++) {
        if (s == NSTG - 1) { CP_WAIT0; } else { CP_WAIT1; }
        __syncthreads();   // slot (s-1)%3 fully consumed by all warps

        if (s + 2 < NSTG) {
            const uint32_t bb = sb + OFF_TILE + wslot * STAGE_B;
            #pragma unroll
            for (int j = 0; j < 4; j++) {
                CP16(bb + T_A + cp_o[j], ap[j]);
                CP16(bb + T_B + cp_o[j], bp[j]);
                ap[j] += KC; bp[j] += KC;
            }
            CP_COMMIT;
        }

        // compute slot rslot — per-kk address = base + (hoisted ^ kk*32)
        const uint32_t abase = sb + OFF_TILE + rslot * STAGE_B + T_A;
        const uint32_t bbase = sb + OFF_TILE + rslot * STAGE_B + T_B;
        #pragma unroll
        for (int kk = 0; kk < 4; kk++) {
            const uint32_t kko = (uint32_t)(kk * 32);
            uint32_t ah[2][4];
            #pragma unroll
            for (int mi = 0; mi < 2; mi++)
                LDSM4(ah[mi], abase + (a_base[mi] ^ kko));
            #pragma unroll
            for (int gp = 0; gp < 2; gp++) {
                uint32_t bh2[2][4];
                #pragma unroll
                for (int gi = 0; gi < 2; gi++)
                    LDSM4(bh2[gi], bbase + (b_base[gp * 2 + gi] ^ kko));
                #pragma unroll
                for (int mi = 0; mi < 2; mi++)
                    #pragma unroll
                    for (int gi = 0; gi < 2; gi++)
                        #pragma unroll
                        for (int sl = 0; sl < 2; sl++) {
                            const int nj = (gp * 2 + gi) * 2 + sl;
                            MMA16816(acc[mi][nj], ah[mi], bh2[gi][sl], bh2[gi][sl + 2]);
                        }
            }
        }

        rslot = (rslot == NBUF - 1) ? 0 : rslot + 1;
        wslot = (wslot == NBUF - 1) ? 0 : wslot + 1;
    }

    // ---- epilogue: tanh(c + qp) * v, row-reduce ----
    #pragma unroll
    for (int mi = 0; mi < 2; mi++)
        #pragma unroll
        for (int hf = 0; hf < 2; hf++) {
            float s = 0.f;
            #pragma unroll
            for (int nj = 0; nj < 8; nj++)
                #pragma unroll
                for (int c = 0; c < 2; c++) {
                    const int h = wn + nj * 8 + ((lane & 3) << 1) + c;
                    const float cc = acc[mi][nj][hf * 2 + c] + qv[h];
                    s += tanh_fast(cc) * vv[h];
                }
            s += __shfl_xor_sync(0xffffffffu, s, 1);
            s += __shfl_xor_sync(0xffffffffu, s, 2);
            if ((lane & 3) == 0)
                sred[(wm + mi * 16 + hf * 8 + (lane >> 2)) * 2 + (warp & 1)] = s;
        }
    __syncthreads();
    if (tid < 128)
        g_part[blockIdx.x * (BSZ * MM) + row0 + tid] = sred[tid * 2] + sred[tid * 2 + 1];
}

// ---------------------------------------------------------------------------
// softmax over M per batch (sums HT h-tile partials), 512 threads
// ---------------------------------------------------------------------------
__global__ __launch_bounds__(512) void softmax_kernel(float* __restrict__ out_w) {
    __shared__ float sm[MM];
    __shared__ float red[512];
    const int b = blockIdx.x, tid = threadIdx.x;
    float lmax = -1e30f;
    for (int m = tid; m < MM; m += 512) {
        float s = 0.f;
        #pragma unroll
        for (int t = 0; t < HT; t++) s += g_part[t * (BSZ * MM) + b * MM + m];
        sm[m] = s;
        lmax = fmaxf(lmax, s);
    }
    red[tid] = lmax; __syncthreads();
    for (int o = 256; o > 0; o >>= 1) {
        if (tid < o) red[tid] = fmaxf(red[tid], red[tid + o]);
        __syncthreads();
    }
    const float mx = red[0];
    __syncthreads();
    float ls = 0.f;
    for (int m = tid; m < MM; m += 512) {
        const float e = expf(sm[m] - mx);
        sm[m] = e; ls += e;
    }
    red[tid] = ls; __syncthreads();
    for (int o = 256; o > 0; o >>= 1) {
        if (tid < o) red[tid] += red[tid + o];
        __syncthreads();
    }
    const float inv = 1.f / red[0];
    for (int m = tid; m < MM; m += 512) out_w[b * MM + m] = sm[m] * inv;
}

// ---------------------------------------------------------------------------
// weighted_memory from the fp16 image, 512 threads (32 m-groups)
// ---------------------------------------------------------------------------
__global__ __launch_bounds__(512) void weighted_mem_kernel(
    const float* __restrict__ w, float* __restrict__ out) {
    __shared__ float wsh[MM];
    __shared__ float sred[8 * 512];   // 16 KB
    const int b = blockIdx.y, d0 = blockIdx.x * 128, tid = threadIdx.x;
    for (int i = tid; i < MM; i += 512) wsh[i] = w[b * MM + i];
    __syncthreads();
    const int lane = tid & 15;        // d-subtile (8 halves)
    const int grp  = tid >> 4;        // 32 m-groups
    const __half* base = g_ah + (size_t)b * MM * DD + d0 + lane * 8;
    float acc[8];
    #pragma unroll
    for (int i = 0; i < 8; i++) acc[i] = 0.f;
    #pragma unroll 4
    for (int m = grp; m < MM; m += 32) {
        const float ww = wsh[m];
        const uint4 x = *(const uint4*)(base + (size_t)m * DD);
        const __half2* hp = (const __half2*)&x;
        #pragma unroll
        for (int p = 0; p < 4; p++) {
            const float2 f = __half22float2(hp[p]);
            acc[2 * p]     = fmaf(ww, f.x, acc[2 * p]);
            acc[2 * p + 1] = fmaf(ww, f.y, acc[2 * p + 1]);
        }
    }
    #pragma unroll
    for (int i = 0; i < 8; i++) sred[i * 512 + tid] = acc[i];
    __syncthreads();
    if (tid < 128) {
        const int lane2 = tid >> 3, i = tid & 7;
        float s = 0.f;
        #pragma unroll
        for (int g = 0; g < 32; g++) s += sred[i * 512 + g * 16 + lane2];
        out[b * DD + d0 + lane2 * 8 + i] = s;
    }
}

// ---------------------------------------------------------------------------
extern "C" void kernel_launch(void* const* d_in, const int* in_sizes, int n_in,
                              void* d_out, int out_size) {
    const float* query  = (const float*)d_in[0];
    const float* memory = (const float*)d_in[1];
    const float* Wq     = (const float*)d_in[2];
    const float* bq     = (const float*)d_in[3];
    const float* Wm     = (const float*)d_in[4];
    const float* v      = (const float*)d_in[5];
    float* out = (float*)d_out;
    float* out_weights = out;                // [BSZ,1,MM]
    float* out_wmem    = out + BSZ * MM;     // [BSZ,1,DD]

    cudaFuncSetAttribute(attn_gemm_hmma,
                         cudaFuncAttributeMaxDynamicSharedMemorySize, SMEM_TOTAL);

    prep_a_kernel<<<(BSZ * MM * DD) / (256 * 16), 256>>>(memory);
    prep_b_kernel<<<HH, 128>>>(Wm);
    qproj_kernel<<<dim3(HH / 64, BSZ / 32), 256>>>(query, Wq, bq);
    attn_gemm_hmma<<<dim3(HT, (BSZ * MM) / 128), 256, SMEM_TOTAL>>>(v);
    softmax_kernel<<<BSZ, 512>>>(out_weights);
    weighted_mem_kernel<<<dim3(DD / 128, BSZ), 512>>>(out_weights, out_wmem);
}